// round 16
// baseline (speedup 1.0000x reference)
#include <cuda_runtime.h>
#include <cuda_bf16.h>
#include <math.h>
#include <stdint.h>

#define B  1024
#define S  200
#define HD 256
#define AD 128

// ---------------- scratch (static device globals; no allocations) ----------
__device__ float g_tproj[B * AD];
__device__ float g_scores[B * S];
__device__ float g_att[S * B];                         // att transposed [t][b]
__device__ __align__(16) float g_X[3ull * S * B * HD]; // [gate][t][b][h]

// bf16 split operands for tensor-core GEMMs
__device__ __align__(16) __nv_bfloat16 g_hsh[(size_t)B * S * HD];
__device__ __align__(16) __nv_bfloat16 g_hsl[(size_t)B * S * HD];
__device__ __align__(16) __nv_bfloat16 g_Wxh[768 * 256];   // [Wr;Wz;Wn] x-part
__device__ __align__(16) __nv_bfloat16 g_Wxl[768 * 256];
__device__ __align__(16) __nv_bfloat16 g_Whh[768 * 256];   // [Wr;Wz;Wn] h-part
__device__ __align__(16) __nv_bfloat16 g_Whl[768 * 256];
__device__ __align__(16) __nv_bfloat16 g_Wsh[128 * 256];   // W1 hidden part
__device__ __align__(16) __nv_bfloat16 g_Wsl[128 * 256];
// recurrence state as bf16 split
__device__ __align__(16) __nv_bfloat16 g_hh[B * HD];
__device__ __align__(16) __nv_bfloat16 g_hl[B * HD];
__device__ __align__(16) __nv_bfloat16 g_rhh[B * HD];
__device__ __align__(16) __nv_bfloat16 g_rhl[B * HD];

static const size_t TB  = (size_t)B * HD;            // 262144
static const size_t XSZ = (size_t)S * B * HD;        // 52,428,800

__device__ __forceinline__ float sigf(float x) { return 1.0f / (1.0f + expf(-x)); }

__device__ __forceinline__ uint32_t smem_u32(const void* p) {
    uint32_t a;
    asm("{ .reg .u64 t; cvta.to.shared.u64 t, %1; cvt.u32.u64 %0, t; }"
        : "=r"(a) : "l"(p));
    return a;
}

__device__ __forceinline__ void ldmat4(uint32_t a[4], uint32_t addr) {
    asm volatile("ldmatrix.sync.aligned.m8n8.x4.shared.b16 {%0,%1,%2,%3}, [%4];"
                 : "=r"(a[0]), "=r"(a[1]), "=r"(a[2]), "=r"(a[3]) : "r"(addr));
}
__device__ __forceinline__ void ldmat2(uint32_t a[2], uint32_t addr) {
    asm volatile("ldmatrix.sync.aligned.m8n8.x2.shared.b16 {%0,%1}, [%2];"
                 : "=r"(a[0]), "=r"(a[1]) : "r"(addr));
}

#define MMA16816(d, a, bb) \
    asm volatile("mma.sync.aligned.m16n8k16.row.col.f32.bf16.bf16.f32 " \
        "{%0,%1,%2,%3}, {%4,%5,%6,%7}, {%8,%9}, {%0,%1,%2,%3};" \
        : "+f"((d)[0]), "+f"((d)[1]), "+f"((d)[2]), "+f"((d)[3]) \
        : "r"((a)[0]), "r"((a)[1]), "r"((a)[2]), "r"((a)[3]), \
          "r"((bb)[0]), "r"((bb)[1]))

#define CLUSTER_ARRIVE() asm volatile("barrier.cluster.arrive.aligned;" ::: "memory")
#define CLUSTER_WAIT()   asm volatile("barrier.cluster.wait.aligned;" ::: "memory")
#define CLUSTER_SYNC() do { CLUSTER_ARRIVE(); CLUSTER_WAIT(); } while (0)

__device__ __forceinline__ void cp16(uint32_t dst, const void* src) {
    asm volatile("cp.async.cg.shared.global [%0], [%1], 16;" :: "r"(dst), "l"(src));
}

// ---------------- fused prep: cvt_hs + cvt_w + tproj ------------------------
__global__ void __launch_bounds__(256) k_prep(
    const float* __restrict__ hs, const float* __restrict__ tgt,
    const float* __restrict__ W1, const float* __restrict__ b1,
    const float* __restrict__ Wr, const float* __restrict__ Wz,
    const float* __restrict__ Wn) {
    __shared__ float4 ts[2][64];
    int bid = blockIdx.x, tid = threadIdx.x;
    if (bid < 51200) {
        size_t i = (size_t)bid * 256 + tid;   // float4 index
        float4 v = ((const float4*)hs)[i];
        union { __nv_bfloat16 b[4]; uint2 u; } H, L;
        H.b[0] = __float2bfloat16(v.x); L.b[0] = __float2bfloat16(v.x - __bfloat162float(H.b[0]));
        H.b[1] = __float2bfloat16(v.y); L.b[1] = __float2bfloat16(v.y - __bfloat162float(H.b[1]));
        H.b[2] = __float2bfloat16(v.z); L.b[2] = __float2bfloat16(v.z - __bfloat162float(H.b[2]));
        H.b[3] = __float2bfloat16(v.w); L.b[3] = __float2bfloat16(v.w - __bfloat162float(H.b[3]));
        ((uint2*)g_hsh)[i] = H.u;
        ((uint2*)g_hsl)[i] = L.u;
    } else if (bid < 52096) {
        int row = bid - 51200, k = tid;
        if (row < 768) {
            int g = row >> 8, c = row & 255;
            const float* W = (g == 0) ? Wr : (g == 1) ? Wz : Wn;
            float v = W[c * 512 + k];
            __nv_bfloat16 h = __float2bfloat16(v);
            g_Wxh[row * 256 + k] = h;
            g_Wxl[row * 256 + k] = __float2bfloat16(v - __bfloat162float(h));
            float v2 = W[c * 512 + 256 + k];
            __nv_bfloat16 h2 = __float2bfloat16(v2);
            g_Whh[row * 256 + k] = h2;
            g_Whl[row * 256 + k] = __float2bfloat16(v2 - __bfloat162float(h2));
        } else {
            int a = row - 768;
            float v = W1[a * 512 + k];
            __nv_bfloat16 h = __float2bfloat16(v);
            g_Wsh[a * 256 + k] = h;
            g_Wsl[a * 256 + k] = __float2bfloat16(v - __bfloat162float(h));
        }
    } else {
        int half = tid >> 7, a = tid & 127;
        int b = (bid - 52096) * 2 + half;
        if (a < 64) ts[half][a] = ((const float4*)(tgt + (size_t)b * HD))[a];
        __syncthreads();
        const float4* w = (const float4*)(W1 + (size_t)a * 512 + 256);
        float s0 = 0.f, s1 = 0.f, s2 = 0.f, s3 = 0.f;
#pragma unroll
        for (int k = 0; k < 64; k += 4) {
            float4 wv, tv;
            wv = w[k];     tv = ts[half][k];     s0 += wv.x*tv.x + wv.y*tv.y + wv.z*tv.z + wv.w*tv.w;
            wv = w[k + 1]; tv = ts[half][k + 1]; s1 += wv.x*tv.x + wv.y*tv.y + wv.z*tv.z + wv.w*tv.w;
            wv = w[k + 2]; tv = ts[half][k + 2]; s2 += wv.x*tv.x + wv.y*tv.y + wv.z*tv.z + wv.w*tv.w;
            wv = w[k + 3]; tv = ts[half][k + 3]; s3 += wv.x*tv.x + wv.y*tv.y + wv.z*tv.z + wv.w*tv.w;
        }
        g_tproj[b * AD + a] = b1[a] + ((s0 + s1) + (s2 + s3));
    }
}

// =========== mma.sync bf16-split GEMM mainloop (128x128, Klog=768) =========
// cp.async.cg triple-buffered: buffer kc ready at iter kc; kc+1, kc+2 in
// flight -> each chunk has ~2 MMA blocks of cover.
__device__ __forceinline__ void gemm_ml(
    const __nv_bfloat16* __restrict__ Ah, const __nv_bfloat16* __restrict__ Al,
    const __nv_bfloat16* __restrict__ Bh, const __nv_bfloat16* __restrict__ Bl,
    __nv_bfloat16* smA, __nv_bfloat16* smB, float c[2][8][4])
{
    int tid = threadIdx.x, lane = tid & 31, wid = tid >> 5;
    int m0 = (wid & 3) * 32, n0 = (wid >> 2) * 64;
    uint32_t smA_u = smem_u32(smA);
    uint32_t smB_u = smem_u32(smB);
    int r0 = tid >> 2, q = tid & 3;
    uint32_t doff0 = (uint32_t)(r0 * 40 + q * 8) * 2;       // bytes, 16B aligned
    uint32_t doff1 = (uint32_t)((r0 + 64) * 40 + q * 8) * 2;
    size_t soff0 = (size_t)r0 * 256 + q * 8;
    size_t soff1 = (size_t)(r0 + 64) * 256 + q * 8;

    uint32_t boff = ((uint32_t)(n0 + (lane & 7) + ((lane >> 4) << 3))) * 80
                  + ((lane >> 3) & 1) * 16;

#define ISSUE_CHUNK(kn, bf) do { \
    const __nv_bfloat16* As_ = ((kn) < 16) ? Ah : Al; \
    const __nv_bfloat16* Bs_ = ((kn) < 8) ? Bh : (((kn) < 16) ? Bl : Bh); \
    int k0_ = ((kn) & 7) * 32; \
    cp16(smA_u + (uint32_t)(bf) * 10240 + doff0, As_ + soff0 + k0_); \
    cp16(smA_u + (uint32_t)(bf) * 10240 + doff1, As_ + soff1 + k0_); \
    cp16(smB_u + (uint32_t)(bf) * 10240 + doff0, Bs_ + soff0 + k0_); \
    cp16(smB_u + (uint32_t)(bf) * 10240 + doff1, Bs_ + soff1 + k0_); \
    asm volatile("cp.async.commit_group;" ::: "memory"); \
} while (0)

    ISSUE_CHUNK(0, 0);
    ISSUE_CHUNK(1, 1);

    int bC = 0, bI = 2;
    for (int kc = 0; kc < 24; kc++) {
        if (kc < 23) asm volatile("cp.async.wait_group 1;" ::: "memory");
        else         asm volatile("cp.async.wait_group 0;" ::: "memory");
        __syncthreads();
        if (kc < 22) ISSUE_CHUNK(kc + 2, bI);
        uint32_t abase = smA_u + (uint32_t)bC * 10240
                       + (uint32_t)(m0 + (lane & 15)) * 80 + ((lane >> 4) * 8) * 2;
        uint32_t bbase = smB_u + (uint32_t)bC * 10240 + boff;
#pragma unroll
        for (int ks = 0; ks < 2; ks++) {
            uint32_t af0[4], af1[4];
            ldmat4(af0, abase + ks * 32);
            ldmat4(af1, abase + 16 * 80 + ks * 32);
            uint32_t bfr[16];
            ldmat4(bfr + 0,  bbase + ks * 32);
            ldmat4(bfr + 4,  bbase + 16 * 80 + ks * 32);
            ldmat4(bfr + 8,  bbase + 32 * 80 + ks * 32);
            ldmat4(bfr + 12, bbase + 48 * 80 + ks * 32);
#pragma unroll
            for (int nf = 0; nf < 8; nf++) {
                uint32_t bb[2] = { bfr[nf * 2], bfr[nf * 2 + 1] };
                MMA16816(c[0][nf], af0, bb);
                MMA16816(c[1][nf], af1, bb);
            }
        }
        bC = (bC + 1 == 3) ? 0 : bC + 1;
        bI = (bI + 1 == 3) ? 0 : bI + 1;
    }
#undef ISSUE_CHUNK
}

// ---------------- attention scores via mma.sync (shuffle epilogue) ---------
__global__ void __launch_bounds__(256, 2) k_scores_mma(const float* __restrict__ W2) {
    extern __shared__ __align__(16) char dsm[];
    __nv_bfloat16* smA = (__nv_bfloat16*)dsm;
    __nv_bfloat16* smB = smA + 3 * 5120;
    float* tpc = (float*)(dsm + 61440);     // [2][128]
    float* w2c = tpc + 256;                 // [128]
    float* red = w2c + 128;                 // [128][2]
    int mtile = blockIdx.x;

    float c[2][8][4];
#pragma unroll
    for (int i = 0; i < 2; i++)
#pragma unroll
        for (int j = 0; j < 8; j++)
#pragma unroll
            for (int e = 0; e < 4; e++) c[i][j][e] = 0.0f;

    gemm_ml(g_hsh + (size_t)mtile * 128 * 256, g_hsl + (size_t)mtile * 128 * 256,
            g_Wsh, g_Wsl, smA, smB, c);

    int tid = threadIdx.x, lane = tid & 31, wid = tid >> 5;
    int m0 = (wid & 3) * 32, n0 = (wid >> 2) * 64;
    int rgb = mtile * 128;
    int bmin = rgb / 200;

    {
        int rrow = tid >> 7, col = tid & 127;
        int bb = bmin + rrow; if (bb > B - 1) bb = B - 1;
        tpc[tid] = g_tproj[bb * 128 + col];
        if (tid < 128) w2c[tid] = W2[tid];
    }
    __syncthreads();

#pragma unroll
    for (int mf = 0; mf < 2; mf++)
#pragma unroll
        for (int p = 0; p < 2; p++) {
            int rloc = m0 + mf * 16 + (lane >> 2) + p * 8;
            int bloc = (rgb + rloc) / 200 - bmin;
            float s = 0.0f;
#pragma unroll
            for (int nf = 0; nf < 8; nf++) {
#pragma unroll
                for (int c2 = 0; c2 < 2; c2++) {
                    int col = n0 + nf * 8 + (lane & 3) * 2 + c2;
                    s += fmaxf(c[mf][nf][2 * p + c2] + tpc[bloc * 128 + col], 0.0f) * w2c[col];
                }
            }
            s += __shfl_xor_sync(0xffffffffu, s, 1);
            s += __shfl_xor_sync(0xffffffffu, s, 2);
            if ((lane & 3) == 0) red[rloc * 2 + (wid >> 2)] = s;
        }
    __syncthreads();
    if (tid < 128)
        g_scores[mtile * 128 + tid] = red[tid * 2] + red[tid * 2 + 1];
}

// ---------------- X projection via mma.sync --------------------------------
__global__ void __launch_bounds__(256) k_xproj_mma(
    const float* __restrict__ br, const float* __restrict__ bz,
    const float* __restrict__ bn) {
    extern __shared__ __align__(16) char dsm[];
    __nv_bfloat16* smA = (__nv_bfloat16*)dsm;
    __nv_bfloat16* smB = smA + 3 * 5120;
    int ntile = blockIdx.x % 6, mtile = blockIdx.x / 6;

    float c[2][8][4];
#pragma unroll
    for (int i = 0; i < 2; i++)
#pragma unroll
        for (int j = 0; j < 8; j++)
#pragma unroll
            for (int e = 0; e < 4; e++) c[i][j][e] = 0.0f;

    gemm_ml(g_hsh + (size_t)mtile * 128 * 256, g_hsl + (size_t)mtile * 128 * 256,
            g_Wxh + (size_t)ntile * 128 * 256, g_Wxl + (size_t)ntile * 128 * 256,
            smA, smB, c);

    int lane = threadIdx.x & 31, wid = threadIdx.x >> 5;
    int m0 = (wid & 3) * 32, n0 = (wid >> 2) * 64;
    int g = ntile >> 1, h0 = (ntile & 1) * 128;
    const float* bias = (g == 0) ? br : (g == 1) ? bz : bn;
    float2 bv[8];
#pragma unroll
    for (int nf = 0; nf < 8; nf++)
        bv[nf] = *(const float2*)(bias + h0 + n0 + nf * 8 + (lane & 3) * 2);

#pragma unroll
    for (int mf = 0; mf < 2; mf++)
#pragma unroll
        for (int p = 0; p < 2; p++) {
            int rg = mtile * 128 + m0 + mf * 16 + (lane >> 2) + p * 8;
            int b = rg / 200, s = rg - b * 200;
            float* dst = g_X + (size_t)g * XSZ + ((size_t)s * B + b) * 256 + h0;
#pragma unroll
            for (int nf = 0; nf < 8; nf++) {
                float2 o;
                o.x = c[mf][nf][2 * p + 0] + bv[nf].x;
                o.y = c[mf][nf][2 * p + 1] + bv[nf].y;
                *(float2*)(dst + n0 + nf * 8 + (lane & 3) * 2) = o;
            }
        }
}

// =================== persistent AUGRU scan (+fused softmax) ================
// R10 structure exactly: 256 thr, 16 clusters x 8 CTAs, z in CTA-local smem,
// split cluster arrive/wait with hpre + PREF_X in the barrier gaps.
#define P1W 16896   // 64*264
#define P2W 8448    // 32*264

__global__ void __launch_bounds__(256, 1) __cluster_dims__(8, 1, 1)
k_recur2(float* __restrict__ out, const int* __restrict__ lengths) {
    extern __shared__ __align__(16) __nv_bfloat16 sm[];
    __nv_bfloat16* Wp1h = sm;                    // [64][264]
    __nv_bfloat16* Wp1l = sm + P1W;
    __nv_bfloat16* Wp2h = sm + 2 * P1W;          // [32][264]
    __nv_bfloat16* Wp2l = sm + 2 * P1W + P2W;
    __nv_bfloat16* Ash  = sm + 2 * P1W + 2 * P2W; // [64][264]
    __nv_bfloat16* Asl  = Ash + P1W;
    float* zbuf = (float*)(Asl + P1W);            // [64][34]

    int tid = threadIdx.x, lane = tid & 31, wid = tid >> 5;
    int bid = blockIdx.x;
    int rt = bid >> 3, ct = bid & 7;
    int mw = wid & 1, nw = wid >> 1;
    int m0w = mw * 32;
    int n0w1 = nw * 16, n0w2 = nw * 8;
    int zwarp = (nw >= 2);
    int lcol0 = zwarp ? (n0w1 - 32) : n0w1;      // 0 or 16

    // ---- fused masked softmax: one warp per batch row (8 rows/CTA) ----
    {
        int b = rt * 64 + ct * 8 + wid;
        int len = lengths[b];
        float v[7];
        float mx = -3.0e38f;
#pragma unroll
        for (int it = 0; it < 7; it++) {
            int j = lane + it * 32;
            float sc = -3.0e38f;
            if (j < S) sc = (j < len) ? __ldcg(&g_scores[b * S + j]) : -1e9f;
            v[it] = sc;
            mx = fmaxf(mx, sc);
        }
#pragma unroll
        for (int o = 16; o; o >>= 1) mx = fmaxf(mx, __shfl_xor_sync(0xffffffffu, mx, o));
        float sum = 0.0f;
#pragma unroll
        for (int it = 0; it < 7; it++) {
            int j = lane + it * 32;
            float e = (j < S) ? expf(v[it] - mx) : 0.0f;
            v[it] = e;
            sum += e;
        }
#pragma unroll
        for (int o = 16; o; o >>= 1) sum += __shfl_xor_sync(0xffffffffu, sum, o);
        float inv = 1.0f / sum;
#pragma unroll
        for (int it = 0; it < 7; it++) {
            int j = lane + it * 32;
            if (j < S) __stcg(&g_att[j * B + b], v[it] * inv);
        }
    }

    // persistent weights: phase1 = [Wr rows ct*32..+32 ; Wz rows ct*32..+32]
    for (int i = tid; i < 2048; i += 256) {
        int r = i >> 5, u = i & 31;
        int src = (r < 32) ? (ct * 32 + r) : (256 + ct * 32 + (r - 32));
        *(uint4*)&Wp1h[r * 264 + u * 8] = *(const uint4*)&g_Whh[(size_t)src * 256 + u * 8];
        *(uint4*)&Wp1l[r * 264 + u * 8] = *(const uint4*)&g_Whl[(size_t)src * 256 + u * 8];
    }
    for (int i = tid; i < 1024; i += 256) {
        int r = i >> 5, u = i & 31;
        *(uint4*)&Wp2h[r * 264 + u * 8] = *(const uint4*)&g_Whh[(size_t)(512 + ct * 32 + r) * 256 + u * 8];
        *(uint4*)&Wp2l[r * 264 + u * 8] = *(const uint4*)&g_Whl[(size_t)(512 + ct * 32 + r) * 256 + u * 8];
    }
    // zero h state
    {
        int r0 = rt * 64 + ct * 8;
        uint4 zu = make_uint4(0u, 0u, 0u, 0u);
        uint4* hhp = (uint4*)(g_hh + (size_t)r0 * 256);
        uint4* hlp = (uint4*)(g_hl + (size_t)r0 * 256);
        for (int i = tid; i < 256; i += 256) { hhp[i] = zu; hlp[i] = zu; }
    }
    __threadfence();
    CLUSTER_SYNC();

    uint32_t AshU = smem_u32(Ash), AslU = smem_u32(Asl);
    uint32_t W1hU = smem_u32(Wp1h), W1lU = smem_u32(Wp1l);
    uint32_t W2hU = smem_u32(Wp2h), W2lU = smem_u32(Wp2l);
    int rowA = lane >> 2, colq = (lane & 3) * 2;
    uint32_t aoff = (uint32_t)(m0w + (lane & 15)) * 528 + (lane >> 4) * 16;
    uint32_t boff1 = ((uint32_t)(n0w1 + (lane & 7) + ((lane >> 4) << 3))) * 528
                   + ((lane >> 3) & 1) * 16;
    uint32_t boff2 = ((uint32_t)(n0w2 + (lane & 7))) * 528
                   + ((lane >> 3) & 1) * 16;

    float2 xpre[2][2][2];     // [mf][p][nf] phase1 X (Xr for r-warps, Xz for z-warps)
    float2 xnpre[2][2];       // [mf][p] phase2 Xn
    float apre[2][2];

#define PREF_X(tt) do { \
    const float* Xn_ = g_X + 2 * XSZ + (size_t)(tt) * TB; \
    int gcn_ = ct * 32 + n0w2 + colq; \
    for (int mf = 0; mf < 2; mf++) \
        for (int p = 0; p < 2; p++) { \
            int b_ = rt * 64 + m0w + mf * 16 + rowA + p * 8; \
            xnpre[mf][p].x = __ldcg(&Xn_[(size_t)b_ * 256 + gcn_]); \
            xnpre[mf][p].y = __ldcg(&Xn_[(size_t)b_ * 256 + gcn_ + 1]); \
        } \
    const float* X1_ = zwarp ? (g_X + XSZ + (size_t)(tt) * TB) : (g_X + (size_t)(tt) * TB); \
    for (int mf = 0; mf < 2; mf++) \
        for (int p = 0; p < 2; p++) { \
            int b_ = rt * 64 + m0w + mf * 16 + rowA + p * 8; \
            if (zwarp) apre[mf][p] = __ldcg(&g_att[(tt) * B + b_]); \
            for (int nf = 0; nf < 2; nf++) { \
                int gc_ = ct * 32 + lcol0 + nf * 8 + colq; \
                xpre[mf][p][nf].x = __ldcg(&X1_[(size_t)b_ * 256 + gc_]); \
                xpre[mf][p][nf].y = __ldcg(&X1_[(size_t)b_ * 256 + gc_ + 1]); \
            } \
        } \
} while (0)

    PREF_X(0);

    for (int t = 0; t < S; t++) {
        // ---------- phase 1: load h tile ----------
        for (int i = tid; i < 2048; i += 256) {
            int r = i >> 5, u = i & 31;
            int4 vh = __ldcg((const int4*)&g_hh[(size_t)(rt * 64 + r) * 256 + u * 8]);
            int4 vl = __ldcg((const int4*)&g_hl[(size_t)(rt * 64 + r) * 256 + u * 8]);
            *(int4*)&Ash[r * 264 + u * 8] = vh;
            *(int4*)&Asl[r * 264 + u * 8] = vl;
        }
        __syncthreads();

        // ---------- phase 1 GEMM: fused 3-term split (ldmatrix A+B) -------
        float c1[2][2][4];
#pragma unroll
        for (int i = 0; i < 2; i++)
#pragma unroll
            for (int j = 0; j < 2; j++)
#pragma unroll
                for (int e = 0; e < 4; e++) c1[i][j][e] = 0.0f;
#pragma unroll
        for (int kc = 0; kc < 16; kc++) {
            uint32_t ah0[4], ah1[4], al0[4], al1[4];
            ldmat4(ah0, AshU + aoff + kc * 32);
            ldmat4(ah1, AshU + aoff + 16 * 528 + kc * 32);
            ldmat4(al0, AslU + aoff + kc * 32);
            ldmat4(al1, AslU + aoff + 16 * 528 + kc * 32);
            uint32_t bh4[4], bl4[4];
            ldmat4(bh4, W1hU + boff1 + kc * 32);
            ldmat4(bl4, W1lU + boff1 + kc * 32);
#pragma unroll
            for (int nf = 0; nf < 2; nf++) {
                uint32_t bh[2] = { bh4[nf * 2], bh4[nf * 2 + 1] };
                uint32_t bl[2] = { bl4[nf * 2], bl4[nf * 2 + 1] };
                MMA16816(c1[0][nf], ah0, bh); MMA16816(c1[1][nf], ah1, bh);
                MMA16816(c1[0][nf], al0, bh); MMA16816(c1[1][nf], al1, bh);
                MMA16816(c1[0][nf], ah0, bl); MMA16816(c1[1][nf], ah1, bl);
            }
        }

        // ---------- phase 1 epilogue ----------
        if (!zwarp) {
#pragma unroll
            for (int mf = 0; mf < 2; mf++)
#pragma unroll
                for (int p = 0; p < 2; p++) {
                    int m = m0w + mf * 16 + rowA + p * 8;
                    int b = rt * 64 + m;
#pragma unroll
                    for (int nf = 0; nf < 2; nf++) {
                        int hc = ct * 32 + lcol0 + nf * 8 + colq;
                        float h0 = __bfloat162float(Ash[m * 264 + hc])
                                 + __bfloat162float(Asl[m * 264 + hc]);
                        float h1 = __bfloat162float(Ash[m * 264 + hc + 1])
                                 + __bfloat162float(Asl[m * 264 + hc + 1]);
                        float rh0 = sigf(c1[mf][nf][2 * p] + xpre[mf][p][nf].x) * h0;
                        float rh1 = sigf(c1[mf][nf][2 * p + 1] + xpre[mf][p][nf].y) * h1;
                        __nv_bfloat162 hi, lo;
                        hi.x = __float2bfloat16(rh0);
                        hi.y = __float2bfloat16(rh1);
                        lo.x = __float2bfloat16(rh0 - __bfloat162float(hi.x));
                        lo.y = __float2bfloat16(rh1 - __bfloat162float(hi.y));
                        *(__nv_bfloat162*)&g_rhh[(size_t)b * 256 + hc] = hi;
                        *(__nv_bfloat162*)&g_rhl[(size_t)b * 256 + hc] = lo;
                    }
                }
        } else {
#pragma unroll
            for (int mf = 0; mf < 2; mf++)
#pragma unroll
                for (int p = 0; p < 2; p++) {
                    int m = m0w + mf * 16 + rowA + p * 8;
                    float av = apre[mf][p];
#pragma unroll
                    for (int nf = 0; nf < 2; nf++) {
                        int j = lcol0 + nf * 8 + colq;
                        float2 o;
                        o.x = sigf(c1[mf][nf][2 * p] + xpre[mf][p][nf].x) * av;
                        o.y = sigf(c1[mf][nf][2 * p + 1] + xpre[mf][p][nf].y) * av;
                        *(float2*)&zbuf[m * 34 + j] = o;
                    }
                }
        }
        CLUSTER_ARRIVE();

        // hpre capture from local smem, hidden in the barrier gap
        float2 hpre[2][2];
        {
            int gcn = ct * 32 + n0w2 + colq;
#pragma unroll
            for (int mf = 0; mf < 2; mf++)
#pragma unroll
                for (int p = 0; p < 2; p++) {
                    int m = m0w + mf * 16 + rowA + p * 8;
                    hpre[mf][p].x = __bfloat162float(Ash[m * 264 + gcn])
                                  + __bfloat162float(Asl[m * 264 + gcn]);
                    hpre[mf][p].y = __bfloat162float(Ash[m * 264 + gcn + 1])
                                  + __bfloat162float(Asl[m * 264 + gcn + 1]);
                }
        }
        CLUSTER_WAIT();

        // ---------- phase 2: rh tile load ----------
        for (int i = tid; i < 2048; i += 256) {
            int r = i >> 5, u = i & 31;
            int4 vh = __ldcg((const int4*)&g_rhh[(size_t)(rt * 64 + r) * 256 + u * 8]);
            int4 vl = __ldcg((const int4*)&g_rhl[(size_t)(rt * 64 + r) * 256 + u * 8]);
            *(int4*)&Ash[r * 264 + u * 8] = vh;
            *(int4*)&Asl[r * 264 + u * 8] = vl;
        }
        __syncthreads();

        // ---------- phase 2 GEMM: fused 3-term split (ldmatrix A+B) -------
        float c2[2][4];
#pragma unroll
        for (int i = 0; i < 2; i++)
#pragma unroll
            for (int e = 0; e < 4; e++) c2[i][e] = 0.0f;
#pragma unroll
        for (int kc = 0; kc < 16; kc++) {
            uint32_t ah0[4], ah1[4], al0[4], al1[4];
            ldmat4(ah0, AshU + aoff + kc * 32);
            ldmat4(ah1, AshU + aoff + 16 * 528 + kc * 32);
            ldmat4(al0, AslU + aoff + kc * 32);
            ldmat4(al1, AslU + aoff + 16 * 528 + kc * 32);
            uint32_t bh[2], bl[2];
            ldmat2(bh, W2hU + boff2 + kc * 32);
            ldmat2(bl, W2lU + boff2 + kc * 32);
            MMA16816(c2[0], ah0, bh); MMA16816(c2[1], ah1, bh);
            MMA16816(c2[0], al0, bh); MMA16816(c2[1], al1, bh);
            MMA16816(c2[0], ah0, bl); MMA16816(c2[1], ah1, bl);
        }

        // ---------- phase 2 epilogue: n = tanh(c + Xn); h update ----------
        {
            int gcn = ct * 32 + n0w2 + colq;
            int jz = n0w2 + colq;
#pragma unroll
            for (int mf = 0; mf < 2; mf++)
#pragma unroll
                for (int p = 0; p < 2; p++) {
                    int m = m0w + mf * 16 + rowA + p * 8;
                    int b = rt * 64 + m;
                    float n0 = tanhf(c2[mf][2 * p] + xnpre[mf][p].x);
                    float n1 = tanhf(c2[mf][2 * p + 1] + xnpre[mf][p].y);
                    float2 hv = hpre[mf][p];
                    float2 zv = *(float2*)&zbuf[m * 34 + jz];
                    float2 o;
                    o.x = hv.x + zv.x * (n0 - hv.x);
                    o.y = hv.y + zv.y * (n1 - hv.y);
                    if (t < S - 1) {
                        __nv_bfloat162 hi, lo;
                        hi.x = __float2bfloat16(o.x);
                        hi.y = __float2bfloat16(o.y);
                        lo.x = __float2bfloat16(o.x - __bfloat162float(hi.x));
                        lo.y = __float2bfloat16(o.y - __bfloat162float(hi.y));
                        *(__nv_bfloat162*)&g_hh[(size_t)b * 256 + gcn] = hi;
                        *(__nv_bfloat162*)&g_hl[(size_t)b * 256 + gcn] = lo;
                    } else {
                        *(float2*)&out[(size_t)b * 256 + gcn] = o;
                    }
                }
        }
        CLUSTER_ARRIVE();
        if (t + 1 < S) PREF_X(t + 1);   // hide next-step DRAM latency in barrier gap
        CLUSTER_WAIT();
    }
#undef PREF_X
}

// ---------------- launcher -------------------------------------------------
extern "C" void kernel_launch(void* const* d_in, const int* in_sizes, int n_in,
                              void* d_out, int out_size) {
    const float* hs  = (const float*)d_in[0];
    const float* tgt = (const float*)d_in[1];
    const int*   len = (const int*)d_in[2];
    const float* W1  = (const float*)d_in[3];
    const float* b1  = (const float*)d_in[4];
    const float* W2  = (const float*)d_in[5];
    const float* Wr  = (const float*)d_in[6];
    const float* br  = (const float*)d_in[7];
    const float* Wz  = (const float*)d_in[8];
    const float* bz  = (const float*)d_in[9];
    const float* Wn  = (const float*)d_in[10];
    const float* bn  = (const float*)d_in[11];
    float* out = (float*)d_out;
    (void)in_sizes; (void)n_in; (void)out_size;

    cudaFuncSetAttribute(k_recur2, cudaFuncAttributeMaxDynamicSharedMemorySize, 177664);
    cudaFuncSetAttribute(k_scores_mma, cudaFuncAttributeMaxDynamicSharedMemorySize, 64000);
    cudaFuncSetAttribute(k_xproj_mma, cudaFuncAttributeMaxDynamicSharedMemorySize, 61440);

    k_prep<<<52608, 256>>>(hs, tgt, W1, b1, Wr, Wz, Wn);     // idx 0
    k_scores_mma<<<1600, 256, 64000>>>(W2);                  // idx 1
    k_xproj_mma<<<9600, 256, 61440>>>(br, bz, bn);           // idx 2
    k_recur2<<<128, 256, 177664>>>(out, len);                // idx 3 (profiled)
}

// round 17
// speedup vs baseline: 1.0350x; 1.0350x over previous
#include <cuda_runtime.h>
#include <cuda_bf16.h>
#include <math.h>
#include <stdint.h>

#define B  1024
#define S  200
#define HD 256
#define AD 128

// ---------------- scratch (static device globals; no allocations) ----------
__device__ float g_tproj[B * AD];
__device__ float g_scores[B * S];
__device__ float g_att[S * B];                         // att transposed [t][b]
__device__ __align__(16) float g_X[3ull * S * B * HD]; // [gate][t][b][h]

// bf16 split operands for tensor-core GEMMs
__device__ __align__(16) __nv_bfloat16 g_hsh[(size_t)B * S * HD];
__device__ __align__(16) __nv_bfloat16 g_hsl[(size_t)B * S * HD];
__device__ __align__(16) __nv_bfloat16 g_Wxh[768 * 256];   // [Wr;Wz;Wn] x-part
__device__ __align__(16) __nv_bfloat16 g_Wxl[768 * 256];
__device__ __align__(16) __nv_bfloat16 g_Whh[768 * 256];   // [Wr;Wz;Wn] h-part
__device__ __align__(16) __nv_bfloat16 g_Whl[768 * 256];
__device__ __align__(16) __nv_bfloat16 g_Wsh[128 * 256];   // W1 hidden part
__device__ __align__(16) __nv_bfloat16 g_Wsl[128 * 256];
// recurrence state as bf16 split
__device__ __align__(16) __nv_bfloat16 g_hh[B * HD];
__device__ __align__(16) __nv_bfloat16 g_hl[B * HD];
__device__ __align__(16) __nv_bfloat16 g_rhh[B * HD];
__device__ __align__(16) __nv_bfloat16 g_rhl[B * HD];

static const size_t TB  = (size_t)B * HD;            // 262144
static const size_t XSZ = (size_t)S * B * HD;        // 52,428,800

__device__ __forceinline__ float sigf(float x) { return 1.0f / (1.0f + expf(-x)); }

__device__ __forceinline__ uint32_t smem_u32(const void* p) {
    uint32_t a;
    asm("{ .reg .u64 t; cvta.to.shared.u64 t, %1; cvt.u32.u64 %0, t; }"
        : "=r"(a) : "l"(p));
    return a;
}

__device__ __forceinline__ void ldmat4(uint32_t a[4], uint32_t addr) {
    asm volatile("ldmatrix.sync.aligned.m8n8.x4.shared.b16 {%0,%1,%2,%3}, [%4];"
                 : "=r"(a[0]), "=r"(a[1]), "=r"(a[2]), "=r"(a[3]) : "r"(addr));
}
__device__ __forceinline__ void ldmat2(uint32_t a[2], uint32_t addr) {
    asm volatile("ldmatrix.sync.aligned.m8n8.x2.shared.b16 {%0,%1}, [%2];"
                 : "=r"(a[0]), "=r"(a[1]) : "r"(addr));
}

#define MMA16816(d, a, bb) \
    asm volatile("mma.sync.aligned.m16n8k16.row.col.f32.bf16.bf16.f32 " \
        "{%0,%1,%2,%3}, {%4,%5,%6,%7}, {%8,%9}, {%0,%1,%2,%3};" \
        : "+f"((d)[0]), "+f"((d)[1]), "+f"((d)[2]), "+f"((d)[3]) \
        : "r"((a)[0]), "r"((a)[1]), "r"((a)[2]), "r"((a)[3]), \
          "r"((bb)[0]), "r"((bb)[1]))

#define CLUSTER_ARRIVE() asm volatile("barrier.cluster.arrive.aligned;" ::: "memory")
#define CLUSTER_WAIT()   asm volatile("barrier.cluster.wait.aligned;" ::: "memory")
#define CLUSTER_SYNC() do { CLUSTER_ARRIVE(); CLUSTER_WAIT(); } while (0)

__device__ __forceinline__ void cp16(uint32_t dst, const void* src) {
    asm volatile("cp.async.cg.shared.global [%0], [%1], 16;" :: "r"(dst), "l"(src));
}

// ---------------- fused prep: cvt_hs + cvt_w + tproj ------------------------
__global__ void __launch_bounds__(256) k_prep(
    const float* __restrict__ hs, const float* __restrict__ tgt,
    const float* __restrict__ W1, const float* __restrict__ b1,
    const float* __restrict__ Wr, const float* __restrict__ Wz,
    const float* __restrict__ Wn) {
    __shared__ float4 ts[2][64];
    int bid = blockIdx.x, tid = threadIdx.x;
    if (bid < 51200) {
        size_t i = (size_t)bid * 256 + tid;   // float4 index
        float4 v = ((const float4*)hs)[i];
        union { __nv_bfloat16 b[4]; uint2 u; } H, L;
        H.b[0] = __float2bfloat16(v.x); L.b[0] = __float2bfloat16(v.x - __bfloat162float(H.b[0]));
        H.b[1] = __float2bfloat16(v.y); L.b[1] = __float2bfloat16(v.y - __bfloat162float(H.b[1]));
        H.b[2] = __float2bfloat16(v.z); L.b[2] = __float2bfloat16(v.z - __bfloat162float(H.b[2]));
        H.b[3] = __float2bfloat16(v.w); L.b[3] = __float2bfloat16(v.w - __bfloat162float(H.b[3]));
        ((uint2*)g_hsh)[i] = H.u;
        ((uint2*)g_hsl)[i] = L.u;
    } else if (bid < 52096) {
        int row = bid - 51200, k = tid;
        if (row < 768) {
            int g = row >> 8, c = row & 255;
            const float* W = (g == 0) ? Wr : (g == 1) ? Wz : Wn;
            float v = W[c * 512 + k];
            __nv_bfloat16 h = __float2bfloat16(v);
            g_Wxh[row * 256 + k] = h;
            g_Wxl[row * 256 + k] = __float2bfloat16(v - __bfloat162float(h));
            float v2 = W[c * 512 + 256 + k];
            __nv_bfloat16 h2 = __float2bfloat16(v2);
            g_Whh[row * 256 + k] = h2;
            g_Whl[row * 256 + k] = __float2bfloat16(v2 - __bfloat162float(h2));
        } else {
            int a = row - 768;
            float v = W1[a * 512 + k];
            __nv_bfloat16 h = __float2bfloat16(v);
            g_Wsh[a * 256 + k] = h;
            g_Wsl[a * 256 + k] = __float2bfloat16(v - __bfloat162float(h));
        }
    } else {
        int half = tid >> 7, a = tid & 127;
        int b = (bid - 52096) * 2 + half;
        if (a < 64) ts[half][a] = ((const float4*)(tgt + (size_t)b * HD))[a];
        __syncthreads();
        const float4* w = (const float4*)(W1 + (size_t)a * 512 + 256);
        float s0 = 0.f, s1 = 0.f, s2 = 0.f, s3 = 0.f;
#pragma unroll
        for (int k = 0; k < 64; k += 4) {
            float4 wv, tv;
            wv = w[k];     tv = ts[half][k];     s0 += wv.x*tv.x + wv.y*tv.y + wv.z*tv.z + wv.w*tv.w;
            wv = w[k + 1]; tv = ts[half][k + 1]; s1 += wv.x*tv.x + wv.y*tv.y + wv.z*tv.z + wv.w*tv.w;
            wv = w[k + 2]; tv = ts[half][k + 2]; s2 += wv.x*tv.x + wv.y*tv.y + wv.z*tv.z + wv.w*tv.w;
            wv = w[k + 3]; tv = ts[half][k + 3]; s3 += wv.x*tv.x + wv.y*tv.y + wv.z*tv.z + wv.w*tv.w;
        }
        g_tproj[b * AD + a] = b1[a] + ((s0 + s1) + (s2 + s3));
    }
}

// =========== mma.sync bf16-split GEMM mainloop (128x128, Klog=768) =========
// R15 winning version: cp.async.cg double-buffered, issue kc+1 before MMAs,
// wait after.
__device__ __forceinline__ void gemm_ml(
    const __nv_bfloat16* __restrict__ Ah, const __nv_bfloat16* __restrict__ Al,
    const __nv_bfloat16* __restrict__ Bh, const __nv_bfloat16* __restrict__ Bl,
    __nv_bfloat16* smA, __nv_bfloat16* smB, float c[2][8][4])
{
    int tid = threadIdx.x, lane = tid & 31, wid = tid >> 5;
    int m0 = (wid & 3) * 32, n0 = (wid >> 2) * 64;
    uint32_t smA_u = smem_u32(smA);
    uint32_t smB_u = smem_u32(smB);
    int r0 = tid >> 2, q = tid & 3;
    uint32_t doff0 = (uint32_t)(r0 * 40 + q * 8) * 2;       // bytes, 16B aligned
    uint32_t doff1 = (uint32_t)((r0 + 64) * 40 + q * 8) * 2;
    size_t soff0 = (size_t)r0 * 256 + q * 8;
    size_t soff1 = (size_t)(r0 + 64) * 256 + q * 8;

    uint32_t boff = ((uint32_t)(n0 + (lane & 7) + ((lane >> 4) << 3))) * 80
                  + ((lane >> 3) & 1) * 16;

#define ISSUE_CHUNK(kn, bf) do { \
    const __nv_bfloat16* As_ = ((kn) < 16) ? Ah : Al; \
    const __nv_bfloat16* Bs_ = ((kn) < 8) ? Bh : (((kn) < 16) ? Bl : Bh); \
    int k0_ = ((kn) & 7) * 32; \
    cp16(smA_u + (uint32_t)(bf) * 10240 + doff0, As_ + soff0 + k0_); \
    cp16(smA_u + (uint32_t)(bf) * 10240 + doff1, As_ + soff1 + k0_); \
    cp16(smB_u + (uint32_t)(bf) * 10240 + doff0, Bs_ + soff0 + k0_); \
    cp16(smB_u + (uint32_t)(bf) * 10240 + doff1, Bs_ + soff1 + k0_); \
    asm volatile("cp.async.commit_group;" ::: "memory"); \
} while (0)

    ISSUE_CHUNK(0, 0);
    asm volatile("cp.async.wait_group 0;" ::: "memory");
    __syncthreads();

    for (int kc = 0; kc < 24; kc++) {
        if (kc < 23) ISSUE_CHUNK(kc + 1, (kc + 1) & 1);
        uint32_t abase = smA_u + (kc & 1) * 10240
                       + (uint32_t)(m0 + (lane & 15)) * 80 + ((lane >> 4) * 8) * 2;
        uint32_t bbase = smB_u + (kc & 1) * 10240 + boff;
#pragma unroll
        for (int ks = 0; ks < 2; ks++) {
            uint32_t af0[4], af1[4];
            ldmat4(af0, abase + ks * 32);
            ldmat4(af1, abase + 16 * 80 + ks * 32);
            uint32_t bfr[16];
            ldmat4(bfr + 0,  bbase + ks * 32);
            ldmat4(bfr + 4,  bbase + 16 * 80 + ks * 32);
            ldmat4(bfr + 8,  bbase + 32 * 80 + ks * 32);
            ldmat4(bfr + 12, bbase + 48 * 80 + ks * 32);
#pragma unroll
            for (int nf = 0; nf < 8; nf++) {
                uint32_t bb[2] = { bfr[nf * 2], bfr[nf * 2 + 1] };
                MMA16816(c[0][nf], af0, bb);
                MMA16816(c[1][nf], af1, bb);
            }
        }
        if (kc < 23) {
            asm volatile("cp.async.wait_group 0;" ::: "memory");
            __syncthreads();
        }
    }
#undef ISSUE_CHUNK
}

// ------------- unified GEMM kernel: xproj (ntile 0..5) + scores (ntile 6) --
__global__ void __launch_bounds__(256, 2) k_gemms(
    const float* __restrict__ br, const float* __restrict__ bz,
    const float* __restrict__ bn, const float* __restrict__ W2) {
    extern __shared__ __align__(16) char dsm[];
    __nv_bfloat16* smA = (__nv_bfloat16*)dsm;
    __nv_bfloat16* smB = smA + 2 * 5120;
    float* tpc = (float*)(dsm + 40960);     // [2][128] (scores path)
    float* w2c = tpc + 256;                 // [128]
    float* red = w2c + 128;                 // [128][2]
    int mtile = blockIdx.x / 7, ntile = blockIdx.x % 7;

    float c[2][8][4];
#pragma unroll
    for (int i = 0; i < 2; i++)
#pragma unroll
        for (int j = 0; j < 8; j++)
#pragma unroll
            for (int e = 0; e < 4; e++) c[i][j][e] = 0.0f;

    const __nv_bfloat16* Bh = (ntile < 6) ? (g_Wxh + (size_t)ntile * 128 * 256) : g_Wsh;
    const __nv_bfloat16* Bl = (ntile < 6) ? (g_Wxl + (size_t)ntile * 128 * 256) : g_Wsl;

    gemm_ml(g_hsh + (size_t)mtile * 128 * 256, g_hsl + (size_t)mtile * 128 * 256,
            Bh, Bl, smA, smB, c);

    int tid = threadIdx.x, lane = tid & 31, wid = tid >> 5;
    int m0 = (wid & 3) * 32, n0 = (wid >> 2) * 64;

    if (ntile < 6) {
        // -------- xproj epilogue --------
        int g = ntile >> 1, h0 = (ntile & 1) * 128;
        const float* bias = (g == 0) ? br : (g == 1) ? bz : bn;
        float2 bv[8];
#pragma unroll
        for (int nf = 0; nf < 8; nf++)
            bv[nf] = *(const float2*)(bias + h0 + n0 + nf * 8 + (lane & 3) * 2);
#pragma unroll
        for (int mf = 0; mf < 2; mf++)
#pragma unroll
            for (int p = 0; p < 2; p++) {
                int rg = mtile * 128 + m0 + mf * 16 + (lane >> 2) + p * 8;
                int b = rg / 200, s = rg - b * 200;
                float* dst = g_X + (size_t)g * XSZ + ((size_t)s * B + b) * 256 + h0;
#pragma unroll
                for (int nf = 0; nf < 8; nf++) {
                    float2 o;
                    o.x = c[mf][nf][2 * p + 0] + bv[nf].x;
                    o.y = c[mf][nf][2 * p + 1] + bv[nf].y;
                    *(float2*)(dst + n0 + nf * 8 + (lane & 3) * 2) = o;
                }
            }
    } else {
        // -------- scores epilogue (shuffle reduction) --------
        int rgb = mtile * 128;
        int bmin = rgb / 200;
        {
            int rrow = tid >> 7, col = tid & 127;
            int bb = bmin + rrow; if (bb > B - 1) bb = B - 1;
            tpc[tid] = g_tproj[bb * 128 + col];
            if (tid < 128) w2c[tid] = W2[tid];
        }
        __syncthreads();
#pragma unroll
        for (int mf = 0; mf < 2; mf++)
#pragma unroll
            for (int p = 0; p < 2; p++) {
                int rloc = m0 + mf * 16 + (lane >> 2) + p * 8;
                int bloc = (rgb + rloc) / 200 - bmin;
                float s = 0.0f;
#pragma unroll
                for (int nf = 0; nf < 8; nf++) {
#pragma unroll
                    for (int c2 = 0; c2 < 2; c2++) {
                        int col = n0 + nf * 8 + (lane & 3) * 2 + c2;
                        s += fmaxf(c[mf][nf][2 * p + c2] + tpc[bloc * 128 + col], 0.0f) * w2c[col];
                    }
                }
                s += __shfl_xor_sync(0xffffffffu, s, 1);
                s += __shfl_xor_sync(0xffffffffu, s, 2);
                if ((lane & 3) == 0) red[rloc * 2 + (wid >> 2)] = s;
            }
        __syncthreads();
        if (tid < 128)
            g_scores[mtile * 128 + tid] = red[tid * 2] + red[tid * 2 + 1];
    }
}

// =================== persistent AUGRU scan (+fused softmax) ================
// R10/R15 structure exactly: 256 thr, 16 clusters x 8 CTAs, z in CTA-local
// smem, split cluster arrive/wait with hpre + PREF_X in the barrier gaps.
#define P1W 16896   // 64*264
#define P2W 8448    // 32*264

__global__ void __launch_bounds__(256, 1) __cluster_dims__(8, 1, 1)
k_recur2(float* __restrict__ out, const int* __restrict__ lengths) {
    extern __shared__ __align__(16) __nv_bfloat16 sm[];
    __nv_bfloat16* Wp1h = sm;                    // [64][264]
    __nv_bfloat16* Wp1l = sm + P1W;
    __nv_bfloat16* Wp2h = sm + 2 * P1W;          // [32][264]
    __nv_bfloat16* Wp2l = sm + 2 * P1W + P2W;
    __nv_bfloat16* Ash  = sm + 2 * P1W + 2 * P2W; // [64][264]
    __nv_bfloat16* Asl  = Ash + P1W;
    float* zbuf = (float*)(Asl + P1W);            // [64][34]

    int tid = threadIdx.x, lane = tid & 31, wid = tid >> 5;
    int bid = blockIdx.x;
    int rt = bid >> 3, ct = bid & 7;
    int mw = wid & 1, nw = wid >> 1;
    int m0w = mw * 32;
    int n0w1 = nw * 16, n0w2 = nw * 8;
    int zwarp = (nw >= 2);
    int lcol0 = zwarp ? (n0w1 - 32) : n0w1;      // 0 or 16

    // ---- fused masked softmax: one warp per batch row (8 rows/CTA) ----
    {
        int b = rt * 64 + ct * 8 + wid;
        int len = lengths[b];
        float v[7];
        float mx = -3.0e38f;
#pragma unroll
        for (int it = 0; it < 7; it++) {
            int j = lane + it * 32;
            float sc = -3.0e38f;
            if (j < S) sc = (j < len) ? __ldcg(&g_scores[b * S + j]) : -1e9f;
            v[it] = sc;
            mx = fmaxf(mx, sc);
        }
#pragma unroll
        for (int o = 16; o; o >>= 1) mx = fmaxf(mx, __shfl_xor_sync(0xffffffffu, mx, o));
        float sum = 0.0f;
#pragma unroll
        for (int it = 0; it < 7; it++) {
            int j = lane + it * 32;
            float e = (j < S) ? expf(v[it] - mx) : 0.0f;
            v[it] = e;
            sum += e;
        }
#pragma unroll
        for (int o = 16; o; o >>= 1) sum += __shfl_xor_sync(0xffffffffu, sum, o);
        float inv = 1.0f / sum;
#pragma unroll
        for (int it = 0; it < 7; it++) {
            int j = lane + it * 32;
            if (j < S) __stcg(&g_att[j * B + b], v[it] * inv);
        }
    }

    // persistent weights: phase1 = [Wr rows ct*32..+32 ; Wz rows ct*32..+32]
    for (int i = tid; i < 2048; i += 256) {
        int r = i >> 5, u = i & 31;
        int src = (r < 32) ? (ct * 32 + r) : (256 + ct * 32 + (r - 32));
        *(uint4*)&Wp1h[r * 264 + u * 8] = *(const uint4*)&g_Whh[(size_t)src * 256 + u * 8];
        *(uint4*)&Wp1l[r * 264 + u * 8] = *(const uint4*)&g_Whl[(size_t)src * 256 + u * 8];
    }
    for (int i = tid; i < 1024; i += 256) {
        int r = i >> 5, u = i & 31;
        *(uint4*)&Wp2h[r * 264 + u * 8] = *(const uint4*)&g_Whh[(size_t)(512 + ct * 32 + r) * 256 + u * 8];
        *(uint4*)&Wp2l[r * 264 + u * 8] = *(const uint4*)&g_Whl[(size_t)(512 + ct * 32 + r) * 256 + u * 8];
    }
    // zero h state
    {
        int r0 = rt * 64 + ct * 8;
        uint4 zu = make_uint4(0u, 0u, 0u, 0u);
        uint4* hhp = (uint4*)(g_hh + (size_t)r0 * 256);
        uint4* hlp = (uint4*)(g_hl + (size_t)r0 * 256);
        for (int i = tid; i < 256; i += 256) { hhp[i] = zu; hlp[i] = zu; }
    }
    __threadfence();
    CLUSTER_SYNC();

    uint32_t AshU = smem_u32(Ash), AslU = smem_u32(Asl);
    uint32_t W1hU = smem_u32(Wp1h), W1lU = smem_u32(Wp1l);
    uint32_t W2hU = smem_u32(Wp2h), W2lU = smem_u32(Wp2l);
    int rowA = lane >> 2, colq = (lane & 3) * 2;
    uint32_t aoff = (uint32_t)(m0w + (lane & 15)) * 528 + (lane >> 4) * 16;
    uint32_t boff1 = ((uint32_t)(n0w1 + (lane & 7) + ((lane >> 4) << 3))) * 528
                   + ((lane >> 3) & 1) * 16;
    uint32_t boff2 = ((uint32_t)(n0w2 + (lane & 7))) * 528
                   + ((lane >> 3) & 1) * 16;

    float2 xpre[2][2][2];     // [mf][p][nf] phase1 X (Xr for r-warps, Xz for z-warps)
    float2 xnpre[2][2];       // [mf][p] phase2 Xn
    float apre[2][2];

#define PREF_X(tt) do { \
    const float* Xn_ = g_X + 2 * XSZ + (size_t)(tt) * TB; \
    int gcn_ = ct * 32 + n0w2 + colq; \
    for (int mf = 0; mf < 2; mf++) \
        for (int p = 0; p < 2; p++) { \
            int b_ = rt * 64 + m0w + mf * 16 + rowA + p * 8; \
            xnpre[mf][p].x = __ldcg(&Xn_[(size_t)b_ * 256 + gcn_]); \
            xnpre[mf][p].y = __ldcg(&Xn_[(size_t)b_ * 256 + gcn_ + 1]); \
        } \
    const float* X1_ = zwarp ? (g_X + XSZ + (size_t)(tt) * TB) : (g_X + (size_t)(tt) * TB); \
    for (int mf = 0; mf < 2; mf++) \
        for (int p = 0; p < 2; p++) { \
            int b_ = rt * 64 + m0w + mf * 16 + rowA + p * 8; \
            if (zwarp) apre[mf][p] = __ldcg(&g_att[(tt) * B + b_]); \
            for (int nf = 0; nf < 2; nf++) { \
                int gc_ = ct * 32 + lcol0 + nf * 8 + colq; \
                xpre[mf][p][nf].x = __ldcg(&X1_[(size_t)b_ * 256 + gc_]); \
                xpre[mf][p][nf].y = __ldcg(&X1_[(size_t)b_ * 256 + gc_ + 1]); \
            } \
        } \
} while (0)

    PREF_X(0);

    for (int t = 0; t < S; t++) {
        // ---------- phase 1: load h tile ----------
        for (int i = tid; i < 2048; i += 256) {
            int r = i >> 5, u = i & 31;
            int4 vh = __ldcg((const int4*)&g_hh[(size_t)(rt * 64 + r) * 256 + u * 8]);
            int4 vl = __ldcg((const int4*)&g_hl[(size_t)(rt * 64 + r) * 256 + u * 8]);
            *(int4*)&Ash[r * 264 + u * 8] = vh;
            *(int4*)&Asl[r * 264 + u * 8] = vl;
        }
        __syncthreads();

        // ---------- phase 1 GEMM: fused 3-term split (ldmatrix A+B) -------
        float c1[2][2][4];
#pragma unroll
        for (int i = 0; i < 2; i++)
#pragma unroll
            for (int j = 0; j < 2; j++)
#pragma unroll
                for (int e = 0; e < 4; e++) c1[i][j][e] = 0.0f;
#pragma unroll
        for (int kc = 0; kc < 16; kc++) {
            uint32_t ah0[4], ah1[4], al0[4], al1[4];
            ldmat4(ah0, AshU + aoff + kc * 32);
            ldmat4(ah1, AshU + aoff + 16 * 528 + kc * 32);
            ldmat4(al0, AslU + aoff + kc * 32);
            ldmat4(al1, AslU + aoff + 16 * 528 + kc * 32);
            uint32_t bh4[4], bl4[4];
            ldmat4(bh4, W1hU + boff1 + kc * 32);
            ldmat4(bl4, W1lU + boff1 + kc * 32);
#pragma unroll
            for (int nf = 0; nf < 2; nf++) {
                uint32_t bh[2] = { bh4[nf * 2], bh4[nf * 2 + 1] };
                uint32_t bl[2] = { bl4[nf * 2], bl4[nf * 2 + 1] };
                MMA16816(c1[0][nf], ah0, bh); MMA16816(c1[1][nf], ah1, bh);
                MMA16816(c1[0][nf], al0, bh); MMA16816(c1[1][nf], al1, bh);
                MMA16816(c1[0][nf], ah0, bl); MMA16816(c1[1][nf], ah1, bl);
            }
        }

        // ---------- phase 1 epilogue ----------
        if (!zwarp) {
#pragma unroll
            for (int mf = 0; mf < 2; mf++)
#pragma unroll
                for (int p = 0; p < 2; p++) {
                    int m = m0w + mf * 16 + rowA + p * 8;
                    int b = rt * 64 + m;
#pragma unroll
                    for (int nf = 0; nf < 2; nf++) {
                        int hc = ct * 32 + lcol0 + nf * 8 + colq;
                        float h0 = __bfloat162float(Ash[m * 264 + hc])
                                 + __bfloat162float(Asl[m * 264 + hc]);
                        float h1 = __bfloat162float(Ash[m * 264 + hc + 1])
                                 + __bfloat162float(Asl[m * 264 + hc + 1]);
                        float rh0 = sigf(c1[mf][nf][2 * p] + xpre[mf][p][nf].x) * h0;
                        float rh1 = sigf(c1[mf][nf][2 * p + 1] + xpre[mf][p][nf].y) * h1;
                        __nv_bfloat162 hi, lo;
                        hi.x = __float2bfloat16(rh0);
                        hi.y = __float2bfloat16(rh1);
                        lo.x = __float2bfloat16(rh0 - __bfloat162float(hi.x));
                        lo.y = __float2bfloat16(rh1 - __bfloat162float(hi.y));
                        *(__nv_bfloat162*)&g_rhh[(size_t)b * 256 + hc] = hi;
                        *(__nv_bfloat162*)&g_rhl[(size_t)b * 256 + hc] = lo;
                    }
                }
        } else {
#pragma unroll
            for (int mf = 0; mf < 2; mf++)
#pragma unroll
                for (int p = 0; p < 2; p++) {
                    int m = m0w + mf * 16 + rowA + p * 8;
                    float av = apre[mf][p];
#pragma unroll
                    for (int nf = 0; nf < 2; nf++) {
                        int j = lcol0 + nf * 8 + colq;
                        float2 o;
                        o.x = sigf(c1[mf][nf][2 * p] + xpre[mf][p][nf].x) * av;
                        o.y = sigf(c1[mf][nf][2 * p + 1] + xpre[mf][p][nf].y) * av;
                        *(float2*)&zbuf[m * 34 + j] = o;
                    }
                }
        }
        CLUSTER_ARRIVE();

        // hpre capture from local smem, hidden in the barrier gap
        float2 hpre[2][2];
        {
            int gcn = ct * 32 + n0w2 + colq;
#pragma unroll
            for (int mf = 0; mf < 2; mf++)
#pragma unroll
                for (int p = 0; p < 2; p++) {
                    int m = m0w + mf * 16 + rowA + p * 8;
                    hpre[mf][p].x = __bfloat162float(Ash[m * 264 + gcn])
                                  + __bfloat162float(Asl[m * 264 + gcn]);
                    hpre[mf][p].y = __bfloat162float(Ash[m * 264 + gcn + 1])
                                  + __bfloat162float(Asl[m * 264 + gcn + 1]);
                }
        }
        CLUSTER_WAIT();

        // ---------- phase 2: rh tile load ----------
        for (int i = tid; i < 2048; i += 256) {
            int r = i >> 5, u = i & 31;
            int4 vh = __ldcg((const int4*)&g_rhh[(size_t)(rt * 64 + r) * 256 + u * 8]);
            int4 vl = __ldcg((const int4*)&g_rhl[(size_t)(rt * 64 + r) * 256 + u * 8]);
            *(int4*)&Ash[r * 264 + u * 8] = vh;
            *(int4*)&Asl[r * 264 + u * 8] = vl;
        }
        __syncthreads();

        // ---------- phase 2 GEMM: fused 3-term split (ldmatrix A+B) -------
        float c2[2][4];
#pragma unroll
        for (int i = 0; i < 2; i++)
#pragma unroll
            for (int e = 0; e < 4; e++) c2[i][e] = 0.0f;
#pragma unroll
        for (int kc = 0; kc < 16; kc++) {
            uint32_t ah0[4], ah1[4], al0[4], al1[4];
            ldmat4(ah0, AshU + aoff + kc * 32);
            ldmat4(ah1, AshU + aoff + 16 * 528 + kc * 32);
            ldmat4(al0, AslU + aoff + kc * 32);
            ldmat4(al1, AslU + aoff + 16 * 528 + kc * 32);
            uint32_t bh[2], bl[2];
            ldmat2(bh, W2hU + boff2 + kc * 32);
            ldmat2(bl, W2lU + boff2 + kc * 32);
            MMA16816(c2[0], ah0, bh); MMA16816(c2[1], ah1, bh);
            MMA16816(c2[0], al0, bh); MMA16816(c2[1], al1, bh);
            MMA16816(c2[0], ah0, bl); MMA16816(c2[1], ah1, bl);
        }

        // ---------- phase 2 epilogue: n = tanh(c + Xn); h update ----------
        {
            int gcn = ct * 32 + n0w2 + colq;
            int jz = n0w2 + colq;
#pragma unroll
            for (int mf = 0; mf < 2; mf++)
#pragma unroll
                for (int p = 0; p < 2; p++) {
                    int m = m0w + mf * 16 + rowA + p * 8;
                    int b = rt * 64 + m;
                    float n0 = tanhf(c2[mf][2 * p] + xnpre[mf][p].x);
                    float n1 = tanhf(c2[mf][2 * p + 1] + xnpre[mf][p].y);
                    float2 hv = hpre[mf][p];
                    float2 zv = *(float2*)&zbuf[m * 34 + jz];
                    float2 o;
                    o.x = hv.x + zv.x * (n0 - hv.x);
                    o.y = hv.y + zv.y * (n1 - hv.y);
                    if (t < S - 1) {
                        __nv_bfloat162 hi, lo;
                        hi.x = __float2bfloat16(o.x);
                        hi.y = __float2bfloat16(o.y);
                        lo.x = __float2bfloat16(o.x - __bfloat162float(hi.x));
                        lo.y = __float2bfloat16(o.y - __bfloat162float(hi.y));
                        *(__nv_bfloat162*)&g_hh[(size_t)b * 256 + gcn] = hi;
                        *(__nv_bfloat162*)&g_hl[(size_t)b * 256 + gcn] = lo;
                    } else {
                        *(float2*)&out[(size_t)b * 256 + gcn] = o;
                    }
                }
        }
        CLUSTER_ARRIVE();
        if (t + 1 < S) PREF_X(t + 1);   // hide next-step DRAM latency in barrier gap
        CLUSTER_WAIT();
    }
#undef PREF_X
}

// ---------------- launcher -------------------------------------------------
extern "C" void kernel_launch(void* const* d_in, const int* in_sizes, int n_in,
                              void* d_out, int out_size) {
    const float* hs  = (const float*)d_in[0];
    const float* tgt = (const float*)d_in[1];
    const int*   len = (const int*)d_in[2];
    const float* W1  = (const float*)d_in[3];
    const float* b1  = (const float*)d_in[4];
    const float* W2  = (const float*)d_in[5];
    const float* Wr  = (const float*)d_in[6];
    const float* br  = (const float*)d_in[7];
    const float* Wz  = (const float*)d_in[8];
    const float* bz  = (const float*)d_in[9];
    const float* Wn  = (const float*)d_in[10];
    const float* bn  = (const float*)d_in[11];
    float* out = (float*)d_out;
    (void)in_sizes; (void)n_in; (void)out_size;

    cudaFuncSetAttribute(k_recur2, cudaFuncAttributeMaxDynamicSharedMemorySize, 177664);
    cudaFuncSetAttribute(k_gemms, cudaFuncAttributeMaxDynamicSharedMemorySize, 43520);

    k_prep<<<52608, 256>>>(hs, tgt, W1, b1, Wr, Wz, Wn);     // idx 0
    k_gemms<<<11200, 256, 43520>>>(br, bz, bn, W2);          // idx 1
    k_recur2<<<128, 256, 177664>>>(out, len);                // idx 2
}